// round 5
// baseline (speedup 1.0000x reference)
#include <cuda_runtime.h>
#include <math.h>

// Shapes: N=1024 nodes, IN=128, H=8 heads, F=16 hidden, out = [1024,128] f32.

__device__ float d_g[1024*128];          // g[i][h*16+f]  (row-major)
__device__ float d_src[1024*8];
__device__ float d_dst[1024*8];
__device__ float d_w[8*1024*1024];       // unnormalized u[h][i][j]  (32 MB)
__device__ float d_zt[1024*8];           // Z_t[i][h]

// packed f32x2 FMA: d = a*b + d (two independent fp32 FMAs per instruction)
#define FMA2(acc, a, b) \
    asm("fma.rn.f32x2 %0, %1, %2, %0;" : "+l"(acc) : "l"(a), "l"(b))

// ---------------------------------------------------------------- kernel A
// 256 blocks x 256 threads; block = 4 rows; thread (t = tid&127, p = tid>>7)
// computes cols t of rows i0+2p, i0+2p+1. 32 independent LDG.128 of W -> MLP.
__global__ void __launch_bounds__(256) k_proj(const float* __restrict__ hin,
                                              const float* __restrict__ W,
                                              const float* __restrict__ aw) {
    int i0 = blockIdx.x * 4;
    int tid = threadIdx.x;
    int t = tid & 127, p = tid >> 7;

    __shared__ float hs[4][128];
    ((float2*)&hs[0][0])[tid] = ((const float2*)(hin + i0 * 128))[tid];
    __syncthreads();

    float a0 = 0.f, a1 = 0.f;
    const float4* wr = (const float4*)(W + t * 128);
    const float4* h0r = (const float4*)&hs[2 * p][0];
    const float4* h1r = (const float4*)&hs[2 * p + 1][0];
    #pragma unroll
    for (int k4 = 0; k4 < 32; ++k4) {
        float4 wq = wr[k4];
        float4 h0 = h0r[k4];
        float4 h1 = h1r[k4];
        a0 = fmaf(wq.x, h0.x, a0); a1 = fmaf(wq.x, h1.x, a1);
        a0 = fmaf(wq.y, h0.y, a0); a1 = fmaf(wq.y, h1.y, a1);
        a0 = fmaf(wq.z, h0.z, a0); a1 = fmaf(wq.z, h1.z, a1);
        a0 = fmaf(wq.w, h0.w, a0); a1 = fmaf(wq.w, h1.w, a1);
    }
    // coalesced row-major stores
    d_g[(i0 + 2 * p) * 128 + t]     = a0;
    d_g[(i0 + 2 * p + 1) * 128 + t] = a1;

    // src/dst: width-16 reductions over f
    int f = t & 15, hd = t >> 4;
    float as = aw[f], ad = aw[16 + f];
    float vs0 = a0 * as, vd0 = a0 * ad, vs1 = a1 * as, vd1 = a1 * ad;
    #pragma unroll
    for (int o = 8; o; o >>= 1) {
        vs0 += __shfl_down_sync(0xffffffffu, vs0, o, 16);
        vd0 += __shfl_down_sync(0xffffffffu, vd0, o, 16);
        vs1 += __shfl_down_sync(0xffffffffu, vs1, o, 16);
        vd1 += __shfl_down_sync(0xffffffffu, vd1, o, 16);
    }
    if (f == 0) {
        d_src[(i0 + 2 * p) * 8 + hd]     = vs0;
        d_dst[(i0 + 2 * p) * 8 + hd]     = vd0;
        d_src[(i0 + 2 * p + 1) * 8 + hd] = vs1;
        d_dst[(i0 + 2 * p + 1) * 8 + hd] = vd1;
    }
}

// ---------------------------------------------------------------- kernel B
__device__ __forceinline__ int SW(int idx) { return idx ^ ((idx >> 5) & 7); }

__device__ __forceinline__ float blockReduce(float v, float* red, bool isMax) {
    int tid = threadIdx.x, lane = tid & 31, warp = tid >> 5;
    __syncthreads();
    #pragma unroll
    for (int o = 16; o; o >>= 1) {
        float u = __shfl_xor_sync(0xffffffffu, v, o);
        v = isMax ? fmaxf(v, u) : v + u;
    }
    if (lane == 0) red[warp] = v;
    __syncthreads();
    if (tid == 0) {
        float a = red[0];
        for (int w = 1; w < 8; ++w) a = isMax ? fmaxf(a, red[w]) : a + red[w];
        red[0] = a;
    }
    __syncthreads();
    return red[0];
}

__device__ __forceinline__ float headReduce(float v, float* red, float* outArr) {
    int tid = threadIdx.x, lane = tid & 31, warp = tid >> 5;
    __syncthreads();
    v += __shfl_xor_sync(0xffffffffu, v, 8);
    v += __shfl_xor_sync(0xffffffffu, v, 16);
    if (lane < 8) red[warp * 8 + lane] = v;
    __syncthreads();
    if (tid < 8) {
        float a = red[tid];
        for (int w = 1; w < 8; ++w) a += red[w * 8 + tid];
        outArr[tid] = a;
    }
    __syncthreads();
    return outArr[tid & 7];
}

// One block (256 thr) per row i; 3 sweeps (m_e via lrelu monotonicity),
// writes unnormalized u to d_w and Z_t to d_zt.
__global__ void __launch_bounds__(256) k_attn(const float* __restrict__ s,
                                              const int* __restrict__ adj) {
    __shared__ float ep[8192];
    __shared__ float sq[1024];
    __shared__ float red[64];
    __shared__ float m_arr[8], z_arr[8];

    int i = blockIdx.x, tid = threadIdx.x;
    int lane = tid & 31, warp = tid >> 5;
    const float NEG = -INFINITY;

    int j0 = tid * 4;
    float4 sv4 = *(const float4*)(s + i * 1024 + j0);
    int4  av4 = *(const int4*)(adj + i * 1024 + j0);
    float svs[4] = {sv4.x, sv4.y, sv4.z, sv4.w};
    int   avs[4] = {av4.x, av4.y, av4.z, av4.w};

    float md[8];
    #pragma unroll
    for (int h = 0; h < 8; ++h) md[h] = NEG;
    float smax = NEG;
    #pragma unroll
    for (int e = 0; e < 4; ++e) {
        float sv = avs[e] ? svs[e] : NEG;
        sq[j0 + e] = sv;
        smax = fmaxf(smax, sv);
        if (avs[e]) {
            float4 d0 = *(const float4*)(d_dst + (j0 + e) * 8);
            float4 d1 = *(const float4*)(d_dst + (j0 + e) * 8 + 4);
            md[0] = fmaxf(md[0], d0.x); md[1] = fmaxf(md[1], d0.y);
            md[2] = fmaxf(md[2], d0.z); md[3] = fmaxf(md[3], d0.w);
            md[4] = fmaxf(md[4], d1.x); md[5] = fmaxf(md[5], d1.y);
            md[6] = fmaxf(md[6], d1.z); md[7] = fmaxf(md[7], d1.w);
        }
    }
    float m_s = blockReduce(smax, red, true);

    #pragma unroll
    for (int o = 16; o; o >>= 1)
        #pragma unroll
        for (int h = 0; h < 8; ++h)
            md[h] = fmaxf(md[h], __shfl_xor_sync(0xffffffffu, md[h], o));
    __syncthreads();
    if (lane == 0)
        #pragma unroll
        for (int h = 0; h < 8; ++h) red[warp * 8 + h] = md[h];
    __syncthreads();
    if (tid < 8) {
        float a = red[tid];
        for (int w = 1; w < 8; ++w) a = fmaxf(a, red[w * 8 + tid]);
        float v = d_src[i * 8 + tid] + a;
        m_arr[tid] = v > 0.f ? v : 0.2f * v;
    }
    __syncthreads();

    int h = tid & 7;
    float m_e  = m_arr[h];
    float srcv = d_src[i * 8 + h];
    float z = 0.f;
    #pragma unroll 4
    for (int it = 0; it < 32; ++it) {
        int idx = tid + 256 * it;
        int j = idx >> 3;
        float e = srcv + d_dst[idx];
        e = e > 0.f ? e : 0.2f * e;
        float p = (sq[j] == NEG) ? 0.f : __expf(e - m_e);
        ep[SW(idx)] = p;
        z += p;
    }
    headReduce(z, red, z_arr);

    float zs = 0.f;
    #pragma unroll
    for (int e = 0; e < 4; ++e) {
        float qv = __expf(sq[j0 + e] - m_s);
        sq[j0 + e] = qv;
        zs += qv;
    }
    float z_s = blockReduce(zs, red, false);
    float invs = 1.0f / z_s;

    int h2 = tid >> 5;
    float inva = 1.0f / z_arr[h2];
    float* wrow = d_w + h2 * 1048576 + i * 1024;
    float zt = 0.f;
    #pragma unroll 4
    for (int it = 0; it < 32; ++it) {
        int j = lane + 32 * it;
        float p = ep[SW(j * 8 + h2)];
        float u = __expf(fmaf(p, inva, sq[j] * invs));
        wrow[j] = u;
        zt += u;
    }
    #pragma unroll
    for (int o = 16; o; o >>= 1) zt += __shfl_xor_sync(0xffffffffu, zt, o);
    if (lane == 0) d_zt[i * 8 + h2] = zt;
}

// ---------------------------------------------------------------- kernel C
// out[i, h*16+f] = (1/Z_t[i,h]) * sum_j u[h][i][j] * g[j][h*16+f]
// grid (32 i-tiles, 8 heads), 256 threads, full-j loop: one plain store per
// output (no memset, no atomics). FFMA2 mainloop.
__global__ void __launch_bounds__(256) k_out(float* __restrict__ out) {
    int it = blockIdx.x, h = blockIdx.y;
    int i0 = it * 32;
    __shared__ float ws[32 * 36];    // [i][32 j], pad stride 36
    __shared__ float gs[16 * 36];    // [f][32 j]

    int tid = threadIdx.x;
    int f = tid & 15, isub = tid >> 4;          // 2 i-rows per thread
    int srow = tid >> 3, sc4 = tid & 7;         // w-staging coords
    int gjl = tid >> 2, gfq = tid & 3;          // g-staging coords (tid<128)
    unsigned long long acc2[2] = {};

    const float* wbase = d_w + h * 1048576 + i0 * 1024;
    const float* gbase = d_g + h * 16;

    for (int ph = 0; ph < 32; ++ph) {
        int jb = ph * 32;
        __syncthreads();
        // stage w chunk [32 i x 32 j] : 256 x float4, coalesced
        *(float4*)(ws + srow * 36 + sc4 * 4) =
            *(const float4*)(wbase + srow * 1024 + jb + sc4 * 4);
        // stage g chunk [16 f x 32 j] from row-major g: 64B/j loads + transpose
        if (tid < 128) {
            float4 gq = *(const float4*)(gbase + (jb + gjl) * 128 + gfq * 4);
            gs[(gfq * 4 + 0) * 36 + gjl] = gq.x;
            gs[(gfq * 4 + 1) * 36 + gjl] = gq.y;
            gs[(gfq * 4 + 2) * 36 + gjl] = gq.z;
            gs[(gfq * 4 + 3) * 36 + gjl] = gq.w;
        }
        __syncthreads();

        #pragma unroll
        for (int j4 = 0; j4 < 8; ++j4) {
            ulonglong2 g2 = *(ulonglong2*)(gs + f * 36 + j4 * 4);
            #pragma unroll
            for (int r = 0; r < 2; ++r) {
                ulonglong2 w2 = *(ulonglong2*)(ws + (isub * 2 + r) * 36 + j4 * 4);
                FMA2(acc2[r], w2.x, g2.x);
                FMA2(acc2[r], w2.y, g2.y);
            }
        }
    }

    #pragma unroll
    for (int r = 0; r < 2; ++r) {
        int i = i0 + isub * 2 + r;
        float lo = __uint_as_float((unsigned)acc2[r]);
        float hi = __uint_as_float((unsigned)(acc2[r] >> 32));
        out[i * 128 + h * 16 + f] = (lo + hi) / d_zt[i * 8 + h];
    }
}

// ---------------------------------------------------------------- launch
extern "C" void kernel_launch(void* const* d_in, const int* in_sizes, int n_in,
                              void* d_out, int out_size) {
    const float* h   = (const float*)d_in[0];
    const int*   adj = (const int*)  d_in[1];
    const float* s   = (const float*)d_in[2];
    const float* W   = (const float*)d_in[3];
    const float* aw  = (const float*)d_in[4];
    float* out = (float*)d_out;

    k_proj<<<256, 256>>>(h, W, aw);
    k_attn<<<1024, 256>>>(s, adj);
    k_out<<<dim3(32, 8), 256>>>(out);
}

// round 7
// speedup vs baseline: 1.1596x; 1.1596x over previous
#include <cuda_runtime.h>
#include <math.h>

// Shapes: N=1024 nodes, IN=128, H=8 heads, F=16 hidden, out = [1024,128] f32.

__device__ float d_WT[128*128];          // WT[k][t] = W[t][k]
__device__ float d_g[1024*128];          // g[i][h*16+f]  (row-major)
__device__ float d_src[1024*8];
__device__ float d_dst[1024*8];
__device__ float d_w[8*1024*1024];       // unnormalized u[h][i][j]  (32 MB)
__device__ float d_zt[1024*8];           // Z_t[i][h]

// packed f32x2 FMA: d = a*b + d (two independent fp32 FMAs per instruction)
#define FMA2(acc, a, b) \
    asm("fma.rn.f32x2 %0, %1, %2, %0;" : "+l"(acc) : "l"(a), "l"(b))

// ---------------------------------------------------------------- kernel A0
__global__ void k_transposeW(const float* __restrict__ W) {
    int idx = blockIdx.x * 1024 + threadIdx.x;          // 16384 total
    d_WT[(idx & 127) * 128 + (idx >> 7)] = W[idx];
}

// ---------------------------------------------------------------- kernel A
// 256 blocks x 256 threads; 4 rows/block, 2 rows/thread.
// WT read is lane-coalesced (stride-1 in t) and L1/L2-resident.
__global__ void __launch_bounds__(256) k_proj(const float* __restrict__ hin,
                                              const float* __restrict__ aw) {
    int i0 = blockIdx.x * 4;
    int tid = threadIdx.x;
    int t = tid & 127, p = tid >> 7;

    __shared__ float hs[4][128];
    ((float2*)&hs[0][0])[tid] = ((const float2*)(hin + i0 * 128))[tid];
    __syncthreads();

    float a0 = 0.f, a1 = 0.f;
    const float* h0 = &hs[2 * p][0];
    const float* h1 = &hs[2 * p + 1][0];
    #pragma unroll 8
    for (int k = 0; k < 128; ++k) {
        float wv = d_WT[k * 128 + t];       // coalesced, 1 line per warp-load
        a0 = fmaf(wv, h0[k], a0);           // hs: broadcast LDS
        a1 = fmaf(wv, h1[k], a1);
    }
    d_g[(i0 + 2 * p) * 128 + t]     = a0;   // coalesced stores
    d_g[(i0 + 2 * p + 1) * 128 + t] = a1;

    int f = t & 15, hd = t >> 4;
    float as = aw[f], ad = aw[16 + f];
    float vs0 = a0 * as, vd0 = a0 * ad, vs1 = a1 * as, vd1 = a1 * ad;
    #pragma unroll
    for (int o = 8; o; o >>= 1) {
        vs0 += __shfl_down_sync(0xffffffffu, vs0, o, 16);
        vd0 += __shfl_down_sync(0xffffffffu, vd0, o, 16);
        vs1 += __shfl_down_sync(0xffffffffu, vs1, o, 16);
        vd1 += __shfl_down_sync(0xffffffffu, vd1, o, 16);
    }
    if (f == 0) {
        d_src[(i0 + 2 * p) * 8 + hd]     = vs0;
        d_dst[(i0 + 2 * p) * 8 + hd]     = vd0;
        d_src[(i0 + 2 * p + 1) * 8 + hd] = vs1;
        d_dst[(i0 + 2 * p + 1) * 8 + hd] = vd1;
    }
}

// ---------------------------------------------------------------- kernel B
__device__ __forceinline__ int SW(int idx) { return idx ^ ((idx >> 5) & 7); }

__device__ __forceinline__ float blockReduce(float v, float* red, bool isMax) {
    int tid = threadIdx.x, lane = tid & 31, warp = tid >> 5;
    __syncthreads();
    #pragma unroll
    for (int o = 16; o; o >>= 1) {
        float u = __shfl_xor_sync(0xffffffffu, v, o);
        v = isMax ? fmaxf(v, u) : v + u;
    }
    if (lane == 0) red[warp] = v;
    __syncthreads();
    if (tid == 0) {
        float a = red[0];
        for (int w = 1; w < 8; ++w) a = isMax ? fmaxf(a, red[w]) : a + red[w];
        red[0] = a;
    }
    __syncthreads();
    return red[0];
}

__device__ __forceinline__ float headReduce(float v, float* red, float* outArr) {
    int tid = threadIdx.x, lane = tid & 31, warp = tid >> 5;
    __syncthreads();
    v += __shfl_xor_sync(0xffffffffu, v, 8);
    v += __shfl_xor_sync(0xffffffffu, v, 16);
    if (lane < 8) red[warp * 8 + lane] = v;
    __syncthreads();
    if (tid < 8) {
        float a = red[tid];
        for (int w = 1; w < 8; ++w) a += red[w * 8 + tid];
        outArr[tid] = a;
    }
    __syncthreads();
    return outArr[tid & 7];
}

// One block (256 thr) per row i; 3 sweeps (m_e via lrelu monotonicity),
// writes unnormalized u to d_w and Z_t to d_zt.
__global__ void __launch_bounds__(256) k_attn(const float* __restrict__ s,
                                              const int* __restrict__ adj) {
    __shared__ float ep[8192];
    __shared__ float sq[1024];
    __shared__ float red[64];
    __shared__ float m_arr[8], z_arr[8];

    int i = blockIdx.x, tid = threadIdx.x;
    int lane = tid & 31, warp = tid >> 5;
    const float NEG = -INFINITY;

    int j0 = tid * 4;
    float4 sv4 = *(const float4*)(s + i * 1024 + j0);
    int4  av4 = *(const int4*)(adj + i * 1024 + j0);
    float svs[4] = {sv4.x, sv4.y, sv4.z, sv4.w};
    int   avs[4] = {av4.x, av4.y, av4.z, av4.w};

    float md[8];
    #pragma unroll
    for (int h = 0; h < 8; ++h) md[h] = NEG;
    float smax = NEG;
    #pragma unroll
    for (int e = 0; e < 4; ++e) {
        float sv = avs[e] ? svs[e] : NEG;
        sq[j0 + e] = sv;
        smax = fmaxf(smax, sv);
        if (avs[e]) {
            float4 d0 = *(const float4*)(d_dst + (j0 + e) * 8);
            float4 d1 = *(const float4*)(d_dst + (j0 + e) * 8 + 4);
            md[0] = fmaxf(md[0], d0.x); md[1] = fmaxf(md[1], d0.y);
            md[2] = fmaxf(md[2], d0.z); md[3] = fmaxf(md[3], d0.w);
            md[4] = fmaxf(md[4], d1.x); md[5] = fmaxf(md[5], d1.y);
            md[6] = fmaxf(md[6], d1.z); md[7] = fmaxf(md[7], d1.w);
        }
    }
    float m_s = blockReduce(smax, red, true);

    #pragma unroll
    for (int o = 16; o; o >>= 1)
        #pragma unroll
        for (int h = 0; h < 8; ++h)
            md[h] = fmaxf(md[h], __shfl_xor_sync(0xffffffffu, md[h], o));
    __syncthreads();
    if (lane == 0)
        #pragma unroll
        for (int h = 0; h < 8; ++h) red[warp * 8 + h] = md[h];
    __syncthreads();
    if (tid < 8) {
        float a = red[tid];
        for (int w = 1; w < 8; ++w) a = fmaxf(a, red[w * 8 + tid]);
        float v = d_src[i * 8 + tid] + a;
        m_arr[tid] = v > 0.f ? v : 0.2f * v;
    }
    __syncthreads();

    int h = tid & 7;
    float m_e  = m_arr[h];
    float srcv = d_src[i * 8 + h];
    float z = 0.f;
    #pragma unroll 4
    for (int it = 0; it < 32; ++it) {
        int idx = tid + 256 * it;
        int j = idx >> 3;
        float e = srcv + d_dst[idx];
        e = e > 0.f ? e : 0.2f * e;
        float p = (sq[j] == NEG) ? 0.f : __expf(e - m_e);
        ep[SW(idx)] = p;
        z += p;
    }
    headReduce(z, red, z_arr);

    float zs = 0.f;
    #pragma unroll
    for (int e = 0; e < 4; ++e) {
        float qv = __expf(sq[j0 + e] - m_s);
        sq[j0 + e] = qv;
        zs += qv;
    }
    float z_s = blockReduce(zs, red, false);
    float invs = 1.0f / z_s;

    int h2 = tid >> 5;
    float inva = 1.0f / z_arr[h2];
    float* wrow = d_w + h2 * 1048576 + i * 1024;
    float zt = 0.f;
    #pragma unroll 4
    for (int it = 0; it < 32; ++it) {
        int j = lane + 32 * it;
        float p = ep[SW(j * 8 + h2)];
        float u = __expf(fmaf(p, inva, sq[j] * invs));
        wrow[j] = u;
        zt += u;
    }
    #pragma unroll
    for (int o = 16; o; o >>= 1) zt += __shfl_xor_sync(0xffffffffu, zt, o);
    if (lane == 0) d_zt[i * 8 + h2] = zt;
}

// ---------------------------------------------------------------- kernel C
// out[i, h*16+f] = (1/Z_t) * sum_j u[h][i][j] * g[j][h*16+f]
// grid (32 i-tiles, 8 heads), 256 thr, STATIC 33KB smem.
// g[f][j] staged per 512-j half; w streamed from gmem (coalesced, 4x dedup).
// j-pair FFMA2 mainloop, shuffle-reduce epilogue, one plain STG.128 per row.
__global__ void __launch_bounds__(256) k_out(float* __restrict__ out) {
    __shared__ float gs[16 * 520];           // [f][512 j], pad stride 520

    int it = blockIdx.x, h = blockIdx.y;
    int tid = threadIdx.x;
    int wid = tid >> 5, lane = tid & 31;
    int jg = lane & 7, fp = lane >> 3;       // 8 j-groups x 4 f-groups
    int i0 = it * 32 + wid * 4;              // 4 rows per warp

    const float* wbase = d_w + h * 1048576 + i0 * 1024;
    unsigned long long acc[4][4] = {};       // [row][f] j-pair partials

    for (int half = 0; half < 2; ++half) {
        int jbase = half * 512;
        __syncthreads();                     // prior-half readers done
        // stage g[jbase..jbase+512), transposed: gs[f][jj]
        for (int jj = tid; jj < 512; jj += 256) {
            const float4* gp = (const float4*)(d_g + (jbase + jj) * 128 + h * 16);
            #pragma unroll
            for (int q = 0; q < 4; ++q) {
                float4 v = gp[q];
                gs[(q * 4 + 0) * 520 + jj] = v.x;
                gs[(q * 4 + 1) * 520 + jj] = v.y;
                gs[(q * 4 + 2) * 520 + jj] = v.z;
                gs[(q * 4 + 3) * 520 + jj] = v.w;
            }
        }
        __syncthreads();

        for (int c = 0; c < 16; ++c) {
            int jo = c * 32 + jg * 4;        // j within half
            ulonglong2 g2[4];
            #pragma unroll
            for (int ff = 0; ff < 4; ++ff)   // 8 lanes/phase, consecutive: no conflicts
                g2[ff] = *(ulonglong2*)(gs + (fp * 4 + ff) * 520 + jo);
            #pragma unroll
            for (int r = 0; r < 4; ++r) {
                ulonglong2 w2 = *(const ulonglong2*)(wbase + r * 1024 + jbase + jo);
                #pragma unroll
                for (int ff = 0; ff < 4; ++ff) {
                    FMA2(acc[r][ff], w2.x, g2[ff].x);
                    FMA2(acc[r][ff], w2.y, g2[ff].y);
                }
            }
        }
    }

    #pragma unroll
    for (int r = 0; r < 4; ++r) {
        float vf[4];
        #pragma unroll
        for (int ff = 0; ff < 4; ++ff) {
            float x = __uint_as_float((unsigned)acc[r][ff]) +
                      __uint_as_float((unsigned)(acc[r][ff] >> 32));
            #pragma unroll
            for (int o = 1; o < 8; o <<= 1)
                x += __shfl_xor_sync(0xffffffffu, x, o);   // reduce over jg
            vf[ff] = x;
        }
        if (jg == 0) {
            int i = i0 + r;
            float inv = 1.0f / d_zt[i * 8 + h];
            *(float4*)(out + i * 128 + h * 16 + fp * 4) =
                make_float4(vf[0] * inv, vf[1] * inv, vf[2] * inv, vf[3] * inv);
        }
    }
}

// ---------------------------------------------------------------- launch
extern "C" void kernel_launch(void* const* d_in, const int* in_sizes, int n_in,
                              void* d_out, int out_size) {
    const float* h   = (const float*)d_in[0];
    const int*   adj = (const int*)  d_in[1];
    const float* s   = (const float*)d_in[2];
    const float* W   = (const float*)d_in[3];
    const float* aw  = (const float*)d_in[4];
    float* out = (float*)d_out;

    k_transposeW<<<16, 1024>>>(W);
    k_proj<<<256, 256>>>(h, aw);
    k_attn<<<1024, 256>>>(s, adj);
    k_out<<<dim3(32, 8), 256>>>(out);
}